// round 14
// baseline (speedup 1.0000x reference)
#include <cuda_runtime.h>
#include <cuda_bf16.h>
#include <stdint.h>

#define BUCKET_SIZE 512
#define G1    296               // pass1 blocks
#define WPB   8                 // warps per block
#define W     (G1 * WPB)        // 2368 warp-tiles
#define RG    64                // row-groups for hierarchical scan
#define RPG   ((W + RG - 1) / RG)   // 37
#define MAXNBP 8192             // padded bucket-row stride (actual nbp = 7816)
#define MAXN  4194304

// Scratch (static; no allocations)
__device__ unsigned char  g_cnt8  [(size_t)W * MAXNBP];          // 19.4MB per-warp-tile counts
__device__ unsigned short g_base16[(size_t)W * MAXNBP];          // 38.8MB clamped absolute bases
__device__ unsigned       g_part  [(size_t)RG * MAXNBP];         //  2MB scan partials
__device__ unsigned       g_word  [MAXN];                        // 16MB  b<<8 | warp-local rank
__device__ unsigned       g_cnt   [MAXNBP];                      // per-bucket totals
__device__ unsigned       g_inv   [(size_t)MAXNBP * BUCKET_SIZE];// 16MB slot -> point idx

// ---- Pass 1: hash + warp-private u8 counting + LOCAL RANK emission ----
__global__ __launch_bounds__(256) void psh_pass1(
    const float* __restrict__ coords, const int* __restrict__ seps,
    const int* __restrict__ hop_p, int n, int nB, int nb, int nbp, int wtile,
    unsigned long long magic_nb, float* __restrict__ out_bucket)
{
    extern __shared__ unsigned char cnt[];   // [WPB][nbp]
    const int lane = threadIdx.x & 31;
    const int wid  = threadIdx.x >> 5;
    for (int j = threadIdx.x; j < (WPB * nbp) >> 2; j += 256)
        ((unsigned*)cnt)[j] = 0u;
    __syncthreads();
    unsigned char* cw = cnt + wid * nbp;

    const unsigned hop = (unsigned)hop_p[0];
    const int wt  = blockIdx.x * WPB + wid;
    const int beg = wt * wtile;
    const int end = min(n, beg + wtile);

    int klo = 0, khi = 0;
    if (beg < end) {
        for (int k = 0; k < nB; k++) {
            int s = __ldg(&seps[k]);
            klo += (s <= beg);
            khi += (s <= end - 1);
        }
    }

    int i = beg + lane;
    bool v = (i < end);
    float x = 0.f, y = 0.f, z = 0.f;
    if (v) { x = coords[3*i]; y = coords[3*i+1]; z = coords[3*i+2]; }

    for (int c = beg; c < end; c += 32) {
        int ni = i + 32;                       // prefetch next chunk
        bool vn = (ni < end);
        float nx = 0.f, ny = 0.f, nz = 0.f;
        if (vn) { nx = coords[3*ni]; ny = coords[3*ni+1]; nz = coords[3*ni+2]; }

        unsigned vm = __ballot_sync(0xffffffffu, v);
        if (v) {
            unsigned bid = (unsigned)klo;
            for (int k = klo; k < khi; k++) bid += (__ldg(&seps[k]) <= i);
            unsigned vx = (unsigned)(int)floorf(x);
            unsigned vy = (unsigned)(int)floorf(y);
            unsigned vz = (unsigned)(int)floorf(z);
            unsigned h = vx * 73856093u ^ vy * 19349663u ^ vz * 83492791u
                       ^ bid * 2654435761u;
            h += hop;
            unsigned q = (unsigned)__umul64hi((unsigned long long)h, magic_nb);
            unsigned b = h - q * (unsigned)nb;
            out_bucket[i] = (float)b;
            unsigned mask = __match_any_sync(vm, b);
            int leader = __ffs(mask) - 1;
            unsigned local = 0;
            if (lane == leader) {
                local = cw[b];
                cw[b] = (unsigned char)(local + __popc(mask));
            }
            local = __shfl_sync(mask, local, leader);
            unsigned lr = local + __popc(mask & ((1u << lane) - 1u));
            g_word[i] = (b << 8) | min(lr, 255u);
        }
        i = ni; v = vn; x = nx; y = ny; z = nz;
    }

    // per-warp raw row flush (coalesced u32; own data, warp-sync only)
    __syncwarp();
    const unsigned* src = (const unsigned*)(cnt + wid * nbp);
    unsigned* dst = (unsigned*)(g_cnt8 + (size_t)wt * nbp);
    for (int j = lane; j < (nbp >> 2); j += 32) dst[j] = src[j];
}

// ---- Scan 2a: partial sums per row-group, ILP=4 buckets/thread ----
__global__ __launch_bounds__(256) void psh_pass2a(int nbp)
{
    const int nq = nbp >> 2;
    int q  = blockIdx.x * 256 + threadIdx.x;
    int rg = blockIdx.y;
    if (q >= nq) return;
    int r0 = rg * RPG, r1 = min(W, r0 + RPG);
    unsigned s0 = 0, s1 = 0, s2 = 0, s3 = 0;
    const unsigned* rows = (const unsigned*)g_cnt8;
    #pragma unroll 4
    for (int r = r0; r < r1; r++) {
        unsigned vv = rows[(size_t)r * nq + q];
        s0 += vv & 255u;         s1 += (vv >> 8) & 255u;
        s2 += (vv >> 16) & 255u; s3 += vv >> 24;
    }
    size_t o = (size_t)rg * nbp + q * 4;
    g_part[o] = s0; g_part[o+1] = s1; g_part[o+2] = s2; g_part[o+3] = s3;
}

// ---- Scan 2b: scan the RG partials per bucket; emit counts ----
__global__ __launch_bounds__(256) void psh_pass2b(
    int nb, int nbp, float* __restrict__ out_counts)
{
    int j = blockIdx.x * 256 + threadIdx.x;
    if (j >= nbp) return;
    unsigned carry = 0;
    #pragma unroll
    for (int rg = 0; rg < RG; rg++) {
        size_t o = (size_t)rg * nbp + j;
        unsigned v = g_part[o];
        g_part[o] = carry;
        carry += v;
    }
    if (j < nb) {
        g_cnt[j] = carry;
        out_counts[j] = (float)carry;
    }
}

// ---- Scan 2c: rescan rows -> clamped u16 absolute bases, ILP=4 ----
__global__ __launch_bounds__(256) void psh_pass2c(int nbp)
{
    const int nq = nbp >> 2;
    int q  = blockIdx.x * 256 + threadIdx.x;
    int rg = blockIdx.y;
    if (q >= nq) return;
    int r0 = rg * RPG, r1 = min(W, r0 + RPG);
    size_t o = (size_t)rg * nbp + q * 4;
    unsigned a0 = g_part[o], a1 = g_part[o+1], a2 = g_part[o+2], a3 = g_part[o+3];
    const unsigned* rows = (const unsigned*)g_cnt8;
    #pragma unroll 4
    for (int r = r0; r < r1; r++) {
        uint2 pk;
        pk.x = min(a0, 1024u) | (min(a1, 1024u) << 16);
        pk.y = min(a2, 1024u) | (min(a3, 1024u) << 16);
        *(uint2*)(g_base16 + (size_t)r * nbp + q * 4) = pk;
        unsigned vv = rows[(size_t)r * nq + q];
        a0 += vv & 255u;         a1 += (vv >> 8) & 255u;
        a2 += (vv >> 16) & 255u; a3 += vv >> 24;
    }
}

// ---- Scatter: smem-free streaming (replaces the 69us rank pass) ----
__global__ __launch_bounds__(256) void psh_scatter(
    int n, int nbp, unsigned long long magic_w)
{
    int i = blockIdx.x * 256 + threadIdx.x;
    if (i >= n) return;
    unsigned wd = g_word[i];
    unsigned b  = wd >> 8;
    unsigned lr = wd & 255u;
    unsigned wt = (unsigned)__umul64hi((unsigned long long)i, magic_w);
    unsigned rank = (unsigned)__ldg(&g_base16[(size_t)wt * nbp + b]) + lr;
    if (rank < BUCKET_SIZE)
        g_inv[(size_t)b * BUCKET_SIZE + rank] = (unsigned)i;
}

// ---- Pass 4: gather — coalesced full-sector output writes (proven shape) ----
__global__ __launch_bounds__(256) void psh_pass4(
    const float* __restrict__ coords, int pad_to,
    float* __restrict__ out_coord)
{
    int s = blockIdx.x * 256 + threadIdx.x;
    if (s >= pad_to) return;
    int b = s >> 9;
    int r = s & (BUCKET_SIZE - 1);
    float x = 0.f, y = 0.f, z = 0.f;
    if ((unsigned)r < g_cnt[b]) {
        unsigned i = g_inv[s];
        x = __ldg(&coords[3*i]);
        y = __ldg(&coords[3*i+1]);
        z = __ldg(&coords[3*i+2]);
    }
    out_coord[(size_t)s * 3 + 0] = x;
    out_coord[(size_t)s * 3 + 1] = y;
    out_coord[(size_t)s * 3 + 2] = z;
}

extern "C" void kernel_launch(void* const* d_in, const int* in_sizes, int n_in,
                              void* d_out, int out_size)
{
    const float* coords = (const float*)d_in[0];
    const int*   seps   = (const int*)d_in[1];
    const int*   hop_p  = (const int*)d_in[2];

    const int n  = in_sizes[0] / 3;
    const int nB = in_sizes[1];
    const int pad_to = ((n + BUCKET_SIZE - 1) / BUCKET_SIZE) * BUCKET_SIZE;
    const int nb  = pad_to / BUCKET_SIZE;
    const int nbp = (nb + 7) & ~7;           // padded row stride (mult of 8)
    const int wtile = (n + W - 1) / W;       // 1690 for n=4M

    float* out_coord  = (float*)d_out;
    float* out_counts = out_coord + (size_t)pad_to * 3;
    float* out_bucket = out_counts + nb;

    unsigned long long magic_nb = (~0ULL) / (unsigned)nb + 1ULL;     // h % nb
    unsigned long long magic_w  = (~0ULL) / (unsigned)wtile + 1ULL;  // i / wtile

    size_t shw = (size_t)WPB * nbp;          // ~62.5 KB -> 3 blocks/SM

    static bool attr_set = false;
    if (!attr_set) {
        cudaFuncSetAttribute(psh_pass1,
                             cudaFuncAttributeMaxDynamicSharedMemorySize,
                             WPB * MAXNBP);
        attr_set = true;
    }

    const int nq = nbp >> 2;
    dim3 gscan((nq + 255) / 256, RG);
    psh_pass1<<<G1, 256, shw>>>(coords, seps, hop_p, n, nB, nb, nbp, wtile,
                                magic_nb, out_bucket);
    psh_pass2a<<<gscan, 256>>>(nbp);
    psh_pass2b<<<(nbp + 255) / 256, 256>>>(nb, nbp, out_counts);
    psh_pass2c<<<gscan, 256>>>(nbp);
    psh_scatter<<<(n + 255) / 256, 256>>>(n, nbp, magic_w);
    psh_pass4<<<(pad_to + 255) / 256, 256>>>(coords, pad_to, out_coord);
}

// round 15
// speedup vs baseline: 1.9327x; 1.9327x over previous
#include <cuda_runtime.h>
#include <cuda_bf16.h>
#include <stdint.h>

#define BUCKET_SIZE 512
#define G1    296               // pass1 blocks
#define WPB   8                 // warps per block
#define W     (G1 * WPB)        // 2368 warp-tiles
#define RG    64                // row-groups for hierarchical scan
#define RPG   ((W + RG - 1) / RG)   // 37
#define MAXNBP 8192             // padded bucket-row stride (actual nbp = 7816)
#define MAXN  4194304

// Scratch (static; no allocations)
__device__ unsigned char  g_cnt8  [(size_t)W * MAXNBP];          // 19.4MB per-warp-tile counts
__device__ unsigned short g_base16[(size_t)W * MAXNBP];          // 38.8MB clamped absolute bases
__device__ unsigned       g_part  [(size_t)RG * MAXNBP];         //  2MB scan partials
__device__ unsigned       g_word  [MAXN];                        // 16MB  b<<8 | warp-local rank
__device__ unsigned       g_cnt   [MAXNBP];                      // per-bucket totals
__device__ unsigned       g_inv   [(size_t)MAXNBP * BUCKET_SIZE];// 16MB slot -> point idx

// ---- Pass 1: hash + warp-private u8 counting + local rank WITHOUT shfl ----
// Trick: every lane of a match-group reads cw[b] (LDS broadcast) BEFORE the
// leader's store, so rank = local + intra needs no shuffle; the loop-carried
// chain stays leader-LDS -> leader-STS, identical to the count-only version.
__global__ __launch_bounds__(256) void psh_pass1(
    const float* __restrict__ coords, const int* __restrict__ seps,
    const int* __restrict__ hop_p, int n, int nB, int nb, int nbp, int wtile,
    unsigned long long magic_nb, float* __restrict__ out_bucket)
{
    extern __shared__ unsigned char cnt[];   // [WPB][nbp]
    const int lane = threadIdx.x & 31;
    const int wid  = threadIdx.x >> 5;
    for (int j = threadIdx.x; j < (WPB * nbp) >> 2; j += 256)
        ((unsigned*)cnt)[j] = 0u;
    __syncthreads();
    unsigned char* cw = cnt + wid * nbp;

    const unsigned hop = (unsigned)hop_p[0];
    const int wt  = blockIdx.x * WPB + wid;
    const int beg = wt * wtile;
    const int end = min(n, beg + wtile);

    int klo = 0, khi = 0;
    if (beg < end) {
        for (int k = 0; k < nB; k++) {
            int s = __ldg(&seps[k]);
            klo += (s <= beg);
            khi += (s <= end - 1);
        }
    }

    int i = beg + lane;
    bool v = (i < end);
    float x = 0.f, y = 0.f, z = 0.f;
    if (v) { x = coords[3*i]; y = coords[3*i+1]; z = coords[3*i+2]; }

    for (int c = beg; c < end; c += 32) {
        int ni = i + 32;                       // prefetch next chunk
        bool vn = (ni < end);
        float nx = 0.f, ny = 0.f, nz = 0.f;
        if (vn) { nx = coords[3*ni]; ny = coords[3*ni+1]; nz = coords[3*ni+2]; }

        unsigned vm = __ballot_sync(0xffffffffu, v);
        if (v) {
            unsigned bid = (unsigned)klo;
            for (int k = klo; k < khi; k++) bid += (__ldg(&seps[k]) <= i);
            unsigned vx = (unsigned)(int)floorf(x);
            unsigned vy = (unsigned)(int)floorf(y);
            unsigned vz = (unsigned)(int)floorf(z);
            unsigned h = vx * 73856093u ^ vy * 19349663u ^ vz * 83492791u
                       ^ bid * 2654435761u;
            h += hop;
            unsigned q = (unsigned)__umul64hi((unsigned long long)h, magic_nb);
            unsigned b = h - q * (unsigned)nb;
            out_bucket[i] = (float)b;
            unsigned mask  = __match_any_sync(vm, b);
            unsigned intra = __popc(mask & ((1u << lane) - 1u));
            unsigned local = (unsigned)cw[b];          // all group lanes: broadcast read
            if (lane == (unsigned)(__ffs(mask) - 1))   // leader updates after reads
                cw[b] = (unsigned char)(local + __popc(mask));
            g_word[i] = (b << 8) | min(local + intra, 255u);
        }
        i = ni; v = vn; x = nx; y = ny; z = nz;
    }

    // per-warp raw row flush (coalesced u32; own data, warp-sync only)
    __syncwarp();
    const unsigned* src = (const unsigned*)(cnt + wid * nbp);
    unsigned* dst = (unsigned*)(g_cnt8 + (size_t)wt * nbp);
    for (int j = lane; j < (nbp >> 2); j += 32) dst[j] = src[j];
}

// ---- Scan 2a: partial sums per row-group, ILP=4 buckets/thread ----
__global__ __launch_bounds__(256) void psh_pass2a(int nbp)
{
    const int nq = nbp >> 2;
    int q  = blockIdx.x * 256 + threadIdx.x;
    int rg = blockIdx.y;
    if (q >= nq) return;
    int r0 = rg * RPG, r1 = min(W, r0 + RPG);
    unsigned s0 = 0, s1 = 0, s2 = 0, s3 = 0;
    const unsigned* rows = (const unsigned*)g_cnt8;
    #pragma unroll 4
    for (int r = r0; r < r1; r++) {
        unsigned vv = rows[(size_t)r * nq + q];
        s0 += vv & 255u;         s1 += (vv >> 8) & 255u;
        s2 += (vv >> 16) & 255u; s3 += vv >> 24;
    }
    size_t o = (size_t)rg * nbp + q * 4;
    g_part[o] = s0; g_part[o+1] = s1; g_part[o+2] = s2; g_part[o+3] = s3;
}

// ---- Scan 2b: scan the RG partials per bucket; emit counts ----
__global__ __launch_bounds__(256) void psh_pass2b(
    int nb, int nbp, float* __restrict__ out_counts)
{
    int j = blockIdx.x * 256 + threadIdx.x;
    if (j >= nbp) return;
    unsigned carry = 0;
    #pragma unroll
    for (int rg = 0; rg < RG; rg++) {
        size_t o = (size_t)rg * nbp + j;
        unsigned v = g_part[o];
        g_part[o] = carry;
        carry += v;
    }
    if (j < nb) {
        g_cnt[j] = carry;
        out_counts[j] = (float)carry;
    }
}

// ---- Scan 2c: rescan rows -> clamped u16 absolute bases, ILP=4 ----
__global__ __launch_bounds__(256) void psh_pass2c(int nbp)
{
    const int nq = nbp >> 2;
    int q  = blockIdx.x * 256 + threadIdx.x;
    int rg = blockIdx.y;
    if (q >= nq) return;
    int r0 = rg * RPG, r1 = min(W, r0 + RPG);
    size_t o = (size_t)rg * nbp + q * 4;
    unsigned a0 = g_part[o], a1 = g_part[o+1], a2 = g_part[o+2], a3 = g_part[o+3];
    const unsigned* rows = (const unsigned*)g_cnt8;
    #pragma unroll 4
    for (int r = r0; r < r1; r++) {
        uint2 pk;
        pk.x = min(a0, 1024u) | (min(a1, 1024u) << 16);
        pk.y = min(a2, 1024u) | (min(a3, 1024u) << 16);
        *(uint2*)(g_base16 + (size_t)r * nbp + q * 4) = pk;
        unsigned vv = rows[(size_t)r * nq + q];
        a0 += vv & 255u;         a1 += (vv >> 8) & 255u;
        a2 += (vv >> 16) & 255u; a3 += vv >> 24;
    }
}

// ---- Scatter: smem-free streaming inv emission (replaces 69us rank pass) ----
__global__ __launch_bounds__(256) void psh_scatter(
    int n, int nbp, unsigned long long magic_w)
{
    int i = blockIdx.x * 256 + threadIdx.x;
    if (i >= n) return;
    unsigned wd = g_word[i];
    unsigned b  = wd >> 8;
    unsigned lr = wd & 255u;
    unsigned wt = (unsigned)__umul64hi((unsigned long long)i, magic_w);
    unsigned rank = (unsigned)__ldg(&g_base16[(size_t)wt * nbp + b]) + lr;
    if (rank < BUCKET_SIZE)
        g_inv[(size_t)b * BUCKET_SIZE + rank] = (unsigned)i;
}

// ---- Pass 4: gather — coalesced full-sector output writes (proven shape) ----
__global__ __launch_bounds__(256) void psh_pass4(
    const float* __restrict__ coords, int pad_to,
    float* __restrict__ out_coord)
{
    int s = blockIdx.x * 256 + threadIdx.x;
    if (s >= pad_to) return;
    int b = s >> 9;
    int r = s & (BUCKET_SIZE - 1);
    float x = 0.f, y = 0.f, z = 0.f;
    if ((unsigned)r < g_cnt[b]) {
        unsigned i = g_inv[s];
        x = __ldg(&coords[3*i]);
        y = __ldg(&coords[3*i+1]);
        z = __ldg(&coords[3*i+2]);
    }
    out_coord[(size_t)s * 3 + 0] = x;
    out_coord[(size_t)s * 3 + 1] = y;
    out_coord[(size_t)s * 3 + 2] = z;
}

extern "C" void kernel_launch(void* const* d_in, const int* in_sizes, int n_in,
                              void* d_out, int out_size)
{
    const float* coords = (const float*)d_in[0];
    const int*   seps   = (const int*)d_in[1];
    const int*   hop_p  = (const int*)d_in[2];

    const int n  = in_sizes[0] / 3;
    const int nB = in_sizes[1];
    const int pad_to = ((n + BUCKET_SIZE - 1) / BUCKET_SIZE) * BUCKET_SIZE;
    const int nb  = pad_to / BUCKET_SIZE;
    const int nbp = (nb + 7) & ~7;           // padded row stride (mult of 8)
    const int wtile = (n + W - 1) / W;       // 1690 for n=4M

    float* out_coord  = (float*)d_out;
    float* out_counts = out_coord + (size_t)pad_to * 3;
    float* out_bucket = out_counts + nb;

    unsigned long long magic_nb = (~0ULL) / (unsigned)nb + 1ULL;     // h % nb
    unsigned long long magic_w  = (~0ULL) / (unsigned)wtile + 1ULL;  // i / wtile

    size_t shw = (size_t)WPB * nbp;          // ~62.5 KB -> 3 blocks/SM

    static bool attr_set = false;
    if (!attr_set) {
        cudaFuncSetAttribute(psh_pass1,
                             cudaFuncAttributeMaxDynamicSharedMemorySize,
                             WPB * MAXNBP);
        attr_set = true;
    }

    const int nq = nbp >> 2;
    dim3 gscan((nq + 255) / 256, RG);
    psh_pass1<<<G1, 256, shw>>>(coords, seps, hop_p, n, nB, nb, nbp, wtile,
                                magic_nb, out_bucket);
    psh_pass2a<<<gscan, 256>>>(nbp);
    psh_pass2b<<<(nbp + 255) / 256, 256>>>(nb, nbp, out_counts);
    psh_pass2c<<<gscan, 256>>>(nbp);
    psh_scatter<<<(n + 255) / 256, 256>>>(n, nbp, magic_w);
    psh_pass4<<<(pad_to + 255) / 256, 256>>>(coords, pad_to, out_coord);
}